// round 12
// baseline (speedup 1.0000x reference)
#include <cuda_runtime.h>

// LSTM B=8192, T=512, I=12, H=20 (i,f,g,o), zero init; Linear(H->10) on h_T.
//
// R12 = R11 mapping + latency surgery:
//  - GEMV/epilogue interleave: j=0, j=2, pair0-epilogue, j=1, j=3, pair1 --
//    pair0's shfl+MUFU chain overlaps GEMV(1,3) fma stream.
//  - Dual accumulators per gate row (even/odd k): chain depth 16 -> 8.
//  - TCHUNK=8: staging barrier every 8 steps.
//  - Thread = 2 gate rows x 1 unit x 4 batches, 32 u64 weights in regs.
//    Partner (lane^1) holds other 2 gates; combined via shfl.xor(1).
//  - Block 320 thr = 2 independent 160-thr groups (named barriers), BPB=32,
//    grid=256, __launch_bounds__(320,2).

#define LSTM_H   20
#define LSTM_I   12
#define LSTM_T   512
#define BPB      32
#define THREADS  320
#define GRID     256
#define TCH      8
#define XROW     100   // floats per batch row in xs: 96 data + 4 pad (400B)

typedef unsigned long long u64;
typedef unsigned int       u32;

__device__ __forceinline__ u64 pack2(float lo, float hi) {
    u64 r; asm("mov.b64 %0, {%1, %2};" : "=l"(r) : "f"(lo), "f"(hi)); return r;
}
__device__ __forceinline__ void unpack2(u64 v, float& lo, float& hi) {
    asm("mov.b64 {%0, %1}, %2;" : "=f"(lo), "=f"(hi) : "l"(v));
}
__device__ __forceinline__ u64 fma2(u64 a, u64 b, u64 c) {
    u64 r; asm("fma.rn.f32x2 %0, %1, %2, %3;" : "=l"(r) : "l"(a), "l"(b), "l"(c));
    return r;
}
__device__ __forceinline__ float hadd2(u64 v) {
    float lo, hi; unpack2(v, lo, hi); return lo + hi;
}
__device__ __forceinline__ float tanhA(float x) {
    float y; asm("tanh.approx.f32 %0, %1;" : "=f"(y) : "f"(x)); return y;
}
__device__ __forceinline__ float sigA(float x) {
    return fmaf(tanhA(0.5f * x), 0.5f, 0.5f);
}
__device__ __forceinline__ void cp_async16(u32 smem_dst, const void* gsrc) {
    asm volatile("cp.async.ca.shared.global [%0], [%1], 16;\n"
                 :: "r"(smem_dst), "l"(gsrc) : "memory");
}
__device__ __forceinline__ void cp_commit() {
    asm volatile("cp.async.commit_group;\n" ::: "memory");
}
template<int N>
__device__ __forceinline__ void cp_wait() {
    asm volatile("cp.async.wait_group %0;\n" :: "n"(N) : "memory");
}
__device__ __forceinline__ void group_bar(int id) {
    asm volatile("bar.sync %0, %1;" :: "r"(id), "r"(160) : "memory");
}

// GEMV for one batch: 2 gate rows, dual accumulators each (even/odd k).
__device__ __forceinline__ void gemv2(const u64* __restrict__ xr,
                                      const u64* __restrict__ hr,
                                      const u64* w0, const u64* w1,
                                      u64 binit0, u64 binit1,
                                      float& ga, float& gb)
{
    u64 aE0 = binit0, aO0 = 0, aE1 = binit1, aO1 = 0;
    #pragma unroll
    for (int k = 0; k < 6; k += 2) {
        ulonglong2 xv = *(const ulonglong2*)(xr + k);
        aE0 = fma2(w0[k],   xv.x, aE0); aO0 = fma2(w0[k+1], xv.y, aO0);
        aE1 = fma2(w1[k],   xv.x, aE1); aO1 = fma2(w1[k+1], xv.y, aO1);
    }
    #pragma unroll
    for (int k = 0; k < 10; k += 2) {
        ulonglong2 hv = *(const ulonglong2*)(hr + k);
        aE0 = fma2(w0[6+k],   hv.x, aE0); aO0 = fma2(w0[6+k+1], hv.y, aO0);
        aE1 = fma2(w1[6+k],   hv.x, aE1); aO1 = fma2(w1[6+k+1], hv.y, aO1);
    }
    ga = hadd2(aE0) + hadd2(aO0);
    gb = hadd2(aE1) + hadd2(aO1);
}

// Exchange with partner (lane^1) + cell update + h store for one owned batch.
__device__ __forceinline__ void epipair(int gh, float ownA, float ownB,
                                        float sendA, float sendB,
                                        float& c, float* hdst)
{
    float recvA = __shfl_xor_sync(0xffffffffu, sendA, 1);
    float recvB = __shfl_xor_sync(0xffffffffu, sendB, 1);
    // gh0: own=(i,g), recv=(f,o); gh1: own=(f,o), recv=(i,g)
    float gi = gh ? recvA : ownA;
    float gg = gh ? recvB : ownB;
    float gf = gh ? ownA  : recvA;
    float go = gh ? ownB  : recvB;
    c = sigA(gf) * c + sigA(gi) * tanhA(gg);
    *hdst = sigA(go) * tanhA(c);
}

__global__ void __launch_bounds__(THREADS, 2)
lstm_kernel(const float* __restrict__ x,
            const float* __restrict__ w_ih,
            const float* __restrict__ w_hh,
            const float* __restrict__ b_ih,
            const float* __restrict__ b_hh,
            const float* __restrict__ w_out,
            const float* __restrict__ b_out,
            float* __restrict__ out)
{
    __shared__ __align__(16) float wcomb[80 * 32];           // 10240 B
    __shared__ __align__(16) float hbuf[2][BPB * LSTM_H];    //  5120 B
    __shared__ __align__(16) float xs[2][BPB * XROW];        // 25600 B

    const int tid  = threadIdx.x;
    const int gid  = tid / 160;          // group 0/1 (owns 16 batches)
    const int ltid = tid - gid * 160;
    const int quad = tid / 40;           // 0..7 (global)
    const int r    = tid % 40;
    const int u    = r >> 1;             // unit 0..19
    const int gh   = r & 1;              // 0 -> (i,g), 1 -> (f,o)
    const int b0   = blockIdx.x * BPB;
    const int q4   = quad * 4;
    const int barid = 1 + gid;

    const int row0 = gh ? (20 + u) : u;          // f : i
    const int row1 = gh ? (60 + u) : (40 + u);   // o : g

    // ---- stage combined weight rows into SMEM ----
    for (int i = tid; i < 80 * LSTM_I; i += THREADS) {
        int rr = i / LSTM_I, k = i - rr * LSTM_I;
        wcomb[rr * 32 + k] = w_ih[i];
    }
    for (int i = tid; i < 80 * LSTM_H; i += THREADS) {
        int rr = i / LSTM_H, k = i - rr * LSTM_H;
        wcomb[rr * 32 + 12 + k] = w_hh[i];
    }
    for (int i = tid; i < BPB * LSTM_H; i += THREADS) hbuf[0][i] = 0.f;

    const u64 binit0 = pack2(b_ih[row0] + b_hh[row0], 0.f);
    const u64 binit1 = pack2(b_ih[row1] + b_hh[row1], 0.f);

    // ---- cp.async: group loads its own 16 batches; chunks of 8 steps ----
    const float4* x4 = (const float4*)x;
    const u32 xs_base = (u32)__cvta_generic_to_shared(&xs[0][0]);
    {
        #pragma unroll 1
        for (int e = ltid; e < 16 * 24; e += 160) {
            int bl = e / 24, q = e - bl * 24;
            int b = gid * 16 + bl;
            cp_async16(xs_base + (u32)((b * XROW + q * 4) * 4),
                       x4 + (long)(b0 + b) * 1536 + q);
        }
        cp_commit();
        #pragma unroll 1
        for (int e = ltid; e < 16 * 24; e += 160) {
            int bl = e / 24, q = e - bl * 24;
            int b = gid * 16 + bl;
            cp_async16(xs_base + (u32)((BPB * XROW + b * XROW + q * 4) * 4),
                       x4 + (long)(b0 + b) * 1536 + 24 + q);
        }
        cp_commit();
    }
    cp_wait<1>();          // chunk 0 landed
    __syncthreads();       // wcomb + hbuf + chunk0 visible

    // ---- this thread's 2 gate rows into registers (32 u64 = 64 regs) ----
    u64 w0[16], w1[16];
    {
        const u64* p0 = (const u64*)&wcomb[row0 * 32];
        const u64* p1 = (const u64*)&wcomb[row1 * 32];
        #pragma unroll
        for (int k = 0; k < 16; k++) { w0[k] = p0[k]; w1[k] = p1[k]; }
    }

    float c0 = 0.f, c1 = 0.f;   // my 2 owned batches: q4+2*gh, q4+2*gh+1

    #pragma unroll 1
    for (int t = 0; t < LSTM_T; t++) {
        const int tt = t & (TCH - 1);
        if (tt == 0 && t > 0) {
            cp_wait<0>();          // my group's chunk landed
            group_bar(barid);      // group done reading old buffer
            if (t + TCH < LSTM_T) {
                const int nbuf = ((t >> 3) + 1) & 1;
                #pragma unroll 1
                for (int e = ltid; e < 16 * 24; e += 160) {
                    int bl = e / 24, q = e - bl * 24;
                    int b = gid * 16 + bl;
                    cp_async16(xs_base + (u32)((nbuf * BPB * XROW + b * XROW + q * 4) * 4),
                               x4 + (long)(b0 + b) * 1536 + (long)(t + TCH) * 3 + q);
                }
                cp_commit();
            }
        }

        const int buf = (t >> 3) & 1;
        const int cur = t & 1, nxt = cur ^ 1;

        const float* xb = &xs[buf][tt * 12];
        const float* hb = &hbuf[cur][0];
        float* hn = &hbuf[nxt][0];

        float gA0, gB0, gA1, gB1, gA2, gB2, gA3, gB3;

        // ---- interleaved schedule: j=0, j=2, pair0, j=1, j=3, pair1 ----
        gemv2((const u64*)(xb + (q4 + 0) * XROW), (const u64*)(hb + (q4 + 0) * LSTM_H),
              w0, w1, binit0, binit1, gA0, gB0);
        gemv2((const u64*)(xb + (q4 + 2) * XROW), (const u64*)(hb + (q4 + 2) * LSTM_H),
              w0, w1, binit0, binit1, gA2, gB2);
        {   // pair p=0: batches j=0 (gh0-owned) and j=2 (gh1-owned)
            float ownA  = gh ? gA2 : gA0;
            float ownB  = gh ? gB2 : gB0;
            float sendA = gh ? gA0 : gA2;
            float sendB = gh ? gB0 : gB2;
            epipair(gh, ownA, ownB, sendA, sendB, c0,
                    hn + (q4 + 2 * gh) * LSTM_H + u);
        }
        gemv2((const u64*)(xb + (q4 + 1) * XROW), (const u64*)(hb + (q4 + 1) * LSTM_H),
              w0, w1, binit0, binit1, gA1, gB1);
        gemv2((const u64*)(xb + (q4 + 3) * XROW), (const u64*)(hb + (q4 + 3) * LSTM_H),
              w0, w1, binit0, binit1, gA3, gB3);
        {   // pair p=1: batches j=1 and j=3
            float ownA  = gh ? gA3 : gA1;
            float ownB  = gh ? gB3 : gB1;
            float sendA = gh ? gA1 : gA3;
            float sendB = gh ? gB1 : gB3;
            epipair(gh, ownA, ownB, sendA, sendB, c1,
                    hn + (q4 + 2 * gh + 1) * LSTM_H + u);
        }
        group_bar(barid);
    }

    // ---- output Linear (final h in hbuf[0]; group-local) ----
    {
        const int bl = ltid / 10, k = ltid - (ltid / 10) * 10;  // 16 x 10
        const int b  = gid * 16 + bl;
        float sum = b_out[k];
        #pragma unroll
        for (int j = 0; j < LSTM_H; j++)
            sum = fmaf(hbuf[0][b * LSTM_H + j], w_out[k * LSTM_H + j], sum);
        out[(long)(b0 + b) * 10 + k] = sum;
    }
}

extern "C" void kernel_launch(void* const* d_in, const int* in_sizes, int n_in,
                              void* d_out, int out_size)
{
    const float* x     = (const float*)d_in[0];
    const float* w_ih  = (const float*)d_in[1];
    const float* w_hh  = (const float*)d_in[2];
    const float* b_ih  = (const float*)d_in[3];
    const float* b_hh  = (const float*)d_in[4];
    const float* w_out = (const float*)d_in[5];
    const float* b_out = (const float*)d_in[6];
    float* out = (float*)d_out;

    lstm_kernel<<<GRID, THREADS>>>(x, w_ih, w_hh, b_ih, b_hh, w_out, b_out, out);
}